// round 4
// baseline (speedup 1.0000x reference)
#include <cuda_runtime.h>
#include <math.h>

#define BB 4
#define CC 64
#define HH 128
#define WW 128
#define OO 64
#define NKK 9
#define QDIM 576
#define PIXB 64
#define NPAIR (PIXB*NKK)    // 576
#define SPX 65              // k_main s pitch: s[c][px]
#define SPP 68              // k_params patch pitch: sp[px][c]

typedef unsigned long long ull;

__device__ __forceinline__ ull pk2(float lo, float hi) {
    ull r; asm("mov.b64 %0,{%1,%2};" : "=l"(r) : "f"(lo), "f"(hi)); return r;
}
__device__ __forceinline__ float2 upk2(ull v) {
    float2 f; asm("mov.b64 {%0,%1},%2;" : "=f"(f.x), "=f"(f.y) : "l"(v)); return f;
}
__device__ __forceinline__ void fma2(ull& d, ull a, ull b) {
    asm("fma.rn.f32x2 %0,%1,%2,%0;" : "+l"(d) : "l"(a), "l"(b));
}
__device__ __forceinline__ ull mul2(ull a, ull b) {
    ull r; asm("mul.rn.f32x2 %0,%1,%2;" : "=l"(r) : "l"(a), "l"(b)); return r;
}

// ---- device scratch ----
__device__ float g_xT[BB*HH*WW*CC];        // NHWC x
__device__ float g_wT[QDIM*OO];            // wT[kk*64+c][o]
__device__ float g_wpg2[NKK*CC*32];        // pg weights [kk][c][co32]
__device__ float g_params[BB*HH*WW*27];    // [pixel][27]

// ============================================================
__global__ void k_transpose_x(const float* __restrict__ x) {
    __shared__ float tile[64][129];
    int bh = blockIdx.x;
    int b = bh >> 7, h = bh & 127;
    int t = threadIdx.x;
    for (int i = t; i < 64 * 128; i += 256) {
        int c = i >> 7, w = i & 127;
        tile[c][w] = x[((size_t)(b * CC + c) * HH + h) * WW + w];
    }
    __syncthreads();
    for (int i = t; i < 64 * 128; i += 256) {
        int w = i >> 6, c = i & 63;
        g_xT[((size_t)bh * WW + w) * CC + c] = tile[c][w];
    }
}

__global__ void k_transpose_w(const float* __restrict__ wgt) {
    int i = blockIdx.x * 256 + threadIdx.x;
    if (i >= OO * CC * NKK) return;
    int o = i / (CC * NKK);
    int r = i % (CC * NKK);
    int c = r / NKK;
    int kk = r % NKK;
    g_wT[(kk * 64 + c) * OO + o] = wgt[i];
}

__global__ void k_prep_wpg2(const float* __restrict__ pgw) {
    int i = blockIdx.x * 256 + threadIdx.x;     // 9*64*32
    if (i >= NKK * CC * 32) return;
    int co = i & 31;
    int c  = (i >> 5) & 63;
    int kk = i >> 11;
    g_wpg2[i] = (co < 27) ? pgw[co * QDIM + c * 9 + kk] : 0.f;
}

// ============================================================
// Kernel 2: offset/mask conv, f32x2 GEMM. block = 128 px (full row)
// thread tile: 8 co (4 pairs) x 2 px
// ============================================================
__global__ void __launch_bounds__(256) k_params(const float* __restrict__ pgb) {
    __shared__ float sp[128 * SPP];     // patch [px][c]
    __shared__ float swp[64 * 32];      // weights [c][co32]
    int t = threadIdx.x;
    int bh = blockIdx.x;                // 512 = b*H+h
    int b = bh >> 7, h = bh & 127;

    int og = t & 3;                     // co = og*8..og*8+7
    int pg = t >> 2;                    // px = pg*2, pg*2+1
    ull acc[8];                         // [co2(4)][px(2)]
    {
#pragma unroll
        for (int o2 = 0; o2 < 4; o2++) {
            int c0 = og * 8 + 2 * o2;
            float be = (c0 + 0 < 27) ? __ldg(&pgb[c0 + 0]) : 0.f;
            float bo = (c0 + 1 < 27) ? __ldg(&pgb[c0 + 1]) : 0.f;
            ull bv = pk2(be, bo);
            acc[o2 * 2 + 0] = bv;
            acc[o2 * 2 + 1] = bv;
        }
    }
    const float* xb = &g_xT[(size_t)b * HH * WW * CC];

#pragma unroll 1
    for (int kk = 0; kk < NKK; kk++) {
        int dh = kk / 3 - 1, dw = kk % 3 - 1;
        int hh = h + dh;
        __syncthreads();
        // stage patch: 128 px x 16 c4  (2048 items)
#pragma unroll
        for (int it = 0; it < 8; it++) {
            int idx = it * 256 + t;
            int c4 = idx & 15;
            int px = idx >> 4;
            int gw = px + dw;
            float4 v = make_float4(0.f, 0.f, 0.f, 0.f);
            if (hh >= 0 && hh < HH && gw >= 0 && gw < WW)
                v = __ldg((const float4*)&xb[((size_t)hh * WW + gw) * CC + c4 * 4]);
            *(float4*)&sp[px * SPP + c4 * 4] = v;
        }
        // stage weights: 64 c x 32 co = 512 float4
#pragma unroll
        for (int it = 0; it < 2; it++) {
            int idx = it * 256 + t;
            ((float4*)swp)[idx] = __ldg(&((const float4*)g_wpg2)[kk * 512 + idx]);
        }
        __syncthreads();
#pragma unroll 8
        for (int ql = 0; ql < 64; ql++) {
            ulonglong2 wA = *(const ulonglong2*)&swp[ql * 32 + og * 8];
            ulonglong2 wB = *(const ulonglong2*)&swp[ql * 32 + og * 8 + 4];
            float s0 = sp[(pg * 2 + 0) * SPP + ql];
            float s1 = sp[(pg * 2 + 1) * SPP + ql];
            ull S0 = pk2(s0, s0), S1 = pk2(s1, s1);
            fma2(acc[0], wA.x, S0); fma2(acc[1], wA.x, S1);
            fma2(acc[2], wA.y, S0); fma2(acc[3], wA.y, S1);
            fma2(acc[4], wB.x, S0); fma2(acc[5], wB.x, S1);
            fma2(acc[6], wB.y, S0); fma2(acc[7], wB.y, S1);
        }
    }
    // store [px][27]
    float* p0 = &g_params[((size_t)bh * WW + pg * 2) * 27];
    float* p1 = p0 + 27;
#pragma unroll
    for (int o2 = 0; o2 < 4; o2++) {
        int c0 = og * 8 + 2 * o2;
        float2 v0 = upk2(acc[o2 * 2 + 0]);
        float2 v1 = upk2(acc[o2 * 2 + 1]);
        if (c0 + 0 < 27) { p0[c0 + 0] = v0.x; p1[c0 + 0] = v1.x; }
        if (c0 + 1 < 27) { p0[c0 + 1] = v0.y; p1[c0 + 1] = v1.y; }
    }
}

// ============================================================
// Kernel 3: fused gather + GEMM, f32x2. block = 64 px, 256 thr
// thread tile: 8 o (4 pairs) x 2 px
// ============================================================
__global__ void __launch_bounds__(256) k_main(const float* __restrict__ bias,
                                              float* __restrict__ out) {
    extern __shared__ float sm[];
    float* s  = sm;                      // [64 c][SPX px]
    float* sw = sm + 64 * SPX;           // [64 q][64 o]
    float* pw = sw + 64 * 64;            // [4][576]
    int*   pi = (int*)(pw + 4 * NPAIR);  // [4][576]

    int t = threadIdx.x;
    int blk = blockIdx.x;                // 1024
    int wb = (blk & 1) * PIXB;
    int bh = blk >> 1;
    int b = bh >> 7, h = bh & 127;

    // ---- phase A: sampling params for all 576 (px,tap) pairs ----
    for (int pair = t; pair < NPAIR; pair += 256) {
        int kk  = pair >> 6;
        int pix = pair & 63;
        int w = wb + pix;
        const float* pp = &g_params[((size_t)bh * WW + w) * 27];
        float dy = pp[2 * kk];
        float dx = pp[2 * kk + 1];
        float m  = pp[18 + kk];
        float mask = 1.f / (1.f + expf(-m));
        float ys = (float)(h - 1 + kk / 3) + dy;
        float xs = (float)(w - 1 + kk % 3) + dx;
        float y0f = floorf(ys), x0f = floorf(xs);
        float ly = ys - y0f, lx = xs - x0f;
        int y0 = (int)y0f, x0 = (int)x0f;
        float vy0 = (y0 >= 0 && y0 < HH) ? 1.f : 0.f;
        float vy1 = (y0 + 1 >= 0 && y0 + 1 < HH) ? 1.f : 0.f;
        float vx0 = (x0 >= 0 && x0 < WW) ? 1.f : 0.f;
        float vx1 = (x0 + 1 >= 0 && x0 + 1 < WW) ? 1.f : 0.f;
        pw[0 * NPAIR + pair] = (1.f - ly) * (1.f - lx) * mask * vy0 * vx0;
        pw[1 * NPAIR + pair] = (1.f - ly) * lx         * mask * vy0 * vx1;
        pw[2 * NPAIR + pair] = ly * (1.f - lx)         * mask * vy1 * vx0;
        pw[3 * NPAIR + pair] = ly * lx                 * mask * vy1 * vx1;
        pi[0 * NPAIR + pair] = min(max(y0, 0), HH - 1) * WW;
        pi[1 * NPAIR + pair] = min(max(y0 + 1, 0), HH - 1) * WW;
        pi[2 * NPAIR + pair] = min(max(x0, 0), WW - 1);
        pi[3 * NPAIR + pair] = min(max(x0 + 1, 0), WW - 1);
    }

    int og = t & 7;                      // o = og*8..og*8+7
    int pg = t >> 3;                     // px = pg*2, pg*2+1
    ull acc[8];                          // [o2(4)][px(2)]
    {
#pragma unroll
        for (int o2 = 0; o2 < 4; o2++) {
            ull bv = pk2(__ldg(&bias[og * 8 + 2 * o2]), __ldg(&bias[og * 8 + 2 * o2 + 1]));
            acc[o2 * 2 + 0] = bv;
            acc[o2 * 2 + 1] = bv;
        }
    }
    const float* xb = &g_xT[(size_t)b * HH * WW * CC];

#pragma unroll 1
    for (int kk = 0; kk < NKK; kk++) {
        __syncthreads();
        // ---- gather chunk: 64 px x 16 c4 (1024 items), c4-major lanes ----
#pragma unroll
        for (int it = 0; it < 4; it++) {
            int idx = it * 256 + t;
            int c4  = idx & 15;
            int pxl = idx >> 4;
            int pair = kk * 64 + pxl;
            int r0  = pi[0 * NPAIR + pair];
            int r1  = pi[1 * NPAIR + pair];
            int x0c = pi[2 * NPAIR + pair];
            int x1c = pi[3 * NPAIR + pair];
            float w00 = pw[0 * NPAIR + pair];
            float w01 = pw[1 * NPAIR + pair];
            float w10 = pw[2 * NPAIR + pair];
            float w11 = pw[3 * NPAIR + pair];
            ull W00 = pk2(w00, w00), W01 = pk2(w01, w01);
            ull W10 = pk2(w10, w10), W11 = pk2(w11, w11);
            ulonglong2 g00 = __ldg((const ulonglong2*)&xb[(size_t)(r0 + x0c) * CC + c4 * 4]);
            ulonglong2 g01 = __ldg((const ulonglong2*)&xb[(size_t)(r0 + x1c) * CC + c4 * 4]);
            ulonglong2 g10 = __ldg((const ulonglong2*)&xb[(size_t)(r1 + x0c) * CC + c4 * 4]);
            ulonglong2 g11 = __ldg((const ulonglong2*)&xb[(size_t)(r1 + x1c) * CC + c4 * 4]);
            ull vA = mul2(W00, g00.x);
            fma2(vA, W01, g01.x); fma2(vA, W10, g10.x); fma2(vA, W11, g11.x);
            ull vB = mul2(W00, g00.y);
            fma2(vB, W01, g01.y); fma2(vB, W10, g10.y); fma2(vB, W11, g11.y);
            float2 fA = upk2(vA), fB = upk2(vB);
            s[(c4 * 4 + 0) * SPX + pxl] = fA.x;
            s[(c4 * 4 + 1) * SPX + pxl] = fA.y;
            s[(c4 * 4 + 2) * SPX + pxl] = fB.x;
            s[(c4 * 4 + 3) * SPX + pxl] = fB.y;
        }
        // ---- stage weight chunk: 64 q x 64 o (1024 float4) ----
#pragma unroll
        for (int it = 0; it < 4; it++) {
            int idx = it * 256 + t;
            ((float4*)sw)[idx] = __ldg(&((const float4*)g_wT)[kk * 1024 + idx]);
        }
        __syncthreads();
        // ---- GEMM chunk ----
#pragma unroll 8
        for (int ql = 0; ql < 64; ql++) {
            ulonglong2 wA = *(const ulonglong2*)&sw[ql * 64 + og * 8];
            ulonglong2 wB = *(const ulonglong2*)&sw[ql * 64 + og * 8 + 4];
            float s0 = s[ql * SPX + pg * 2];
            float s1 = s[ql * SPX + pg * 2 + 1];
            ull S0 = pk2(s0, s0), S1 = pk2(s1, s1);
            fma2(acc[0], wA.x, S0); fma2(acc[1], wA.x, S1);
            fma2(acc[2], wA.y, S0); fma2(acc[3], wA.y, S1);
            fma2(acc[4], wB.x, S0); fma2(acc[5], wB.x, S1);
            fma2(acc[6], wB.y, S0); fma2(acc[7], wB.y, S1);
        }
    }

    // ---- store: 8 o-planes x 2 px (float2 per o) ----
    int w0 = wb + pg * 2;
    size_t ostride = (size_t)HH * WW;
    size_t base = ((size_t)(b * OO + og * 8) * HH + h) * WW + w0;
#pragma unroll
    for (int o2 = 0; o2 < 4; o2++) {
        float2 v0 = upk2(acc[o2 * 2 + 0]);   // (o even, o odd) @ px0
        float2 v1 = upk2(acc[o2 * 2 + 1]);   // (o even, o odd) @ px1
        float2 se = make_float2(v0.x, v1.x);
        float2 so = make_float2(v0.y, v1.y);
        *(float2*)&out[base + (size_t)(2 * o2 + 0) * ostride] = se;
        *(float2*)&out[base + (size_t)(2 * o2 + 1) * ostride] = so;
    }
}

// ============================================================
extern "C" void kernel_launch(void* const* d_in, const int* in_sizes, int n_in,
                              void* d_out, int out_size) {
    const float* x      = (const float*)d_in[0];
    const float* weight = (const float*)d_in[1];
    const float* bias   = (const float*)d_in[2];
    const float* pg_w   = (const float*)d_in[3];
    const float* pg_b   = (const float*)d_in[4];
    float* out = (float*)d_out;

    const int SMEM_MAIN = (64 * SPX + 64 * 64 + 8 * NPAIR) * 4;   // ~50.3 KB

    cudaFuncSetAttribute(k_main, cudaFuncAttributeMaxDynamicSharedMemorySize, SMEM_MAIN);

    k_transpose_x<<<BB * HH, 256>>>(x);
    k_transpose_w<<<(OO * CC * NKK + 255) / 256, 256>>>(weight);
    k_prep_wpg2<<<(NKK * CC * 32 + 255) / 256, 256>>>(pg_w);
    k_params<<<BB * HH, 256>>>(pg_b);
    k_main<<<BB * HH * (WW / PIXB), 256, SMEM_MAIN>>>(bias, out);
}

// round 7
// speedup vs baseline: 2.3132x; 2.3132x over previous
#include <cuda_runtime.h>
#include <cuda_bf16.h>
#include <math.h>

#define BB 4
#define CC 64
#define HH 128
#define WW 128
#define OO 64
#define NKK 9
#define QDIM 576
#define SPP 68              // k_params patch pitch

typedef unsigned int u32;

// ---- device scratch ----
__device__ float g_xT[BB*HH*WW*CC];             // NHWC x
__device__ float g_wpg2[NKK*CC*32];             // pg weights [kk][c][co32]
__device__ float g_params[BB*HH*WW*27];         // [pixel][27]
__device__ __nv_bfloat16 g_wbH[NKK*OO*CC];      // main weights bf16 hi, [kk][o][c]
__device__ __nv_bfloat16 g_wbL[NKK*OO*CC];      // main weights bf16 lo

__device__ __forceinline__ u32 smem_u32(const void* p) {
    u32 a;
    asm("{ .reg .u64 t; cvta.to.shared.u64 t, %1; cvt.u32.u64 %0, t; }" : "=r"(a) : "l"(p));
    return a;
}

#define LDSM4(r0, r1, r2, r3, addr) \
    asm volatile("ldmatrix.sync.aligned.m8n8.x4.shared.b16 {%0,%1,%2,%3},[%4];" \
        : "=r"(r0), "=r"(r1), "=r"(r2), "=r"(r3) : "r"(addr))

__device__ __forceinline__ void mma16816(float* d, u32 a0, u32 a1, u32 a2, u32 a3,
                                         u32 b0, u32 b1) {
    asm volatile(
        "mma.sync.aligned.m16n8k16.row.col.f32.bf16.bf16.f32 "
        "{%0,%1,%2,%3},{%4,%5,%6,%7},{%8,%9},{%0,%1,%2,%3};"
        : "+f"(d[0]), "+f"(d[1]), "+f"(d[2]), "+f"(d[3])
        : "r"(a0), "r"(a1), "r"(a2), "r"(a3), "r"(b0), "r"(b1));
}

// ============================================================
// Kernel 0: x NCHW -> NHWC
// ============================================================
__global__ void k_transpose_x(const float* __restrict__ x) {
    __shared__ float tile[64][129];
    int bh = blockIdx.x;
    int b = bh >> 7, h = bh & 127;
    int t = threadIdx.x;
    for (int i = t; i < 64 * 128; i += 256) {
        int c = i >> 7, w = i & 127;
        tile[c][w] = x[((size_t)(b * CC + c) * HH + h) * WW + w];
    }
    __syncthreads();
    for (int i = t; i < 64 * 128; i += 256) {
        int w = i >> 6, c = i & 63;
        g_xT[((size_t)bh * WW + w) * CC + c] = tile[c][w];
    }
}

// ============================================================
// Kernel 1: weight (O,C,3,3) -> bf16 hi/lo [kk][o][c]
// ============================================================
__global__ void k_prep_wb(const float* __restrict__ wgt) {
    int i = blockIdx.x * 256 + threadIdx.x;   // 36864
    if (i >= NKK * OO * CC) return;
    int kk = i % 9;
    int c  = (i / 9) & 63;
    int o  = i / (9 * 64);
    float w = wgt[i];
    __nv_bfloat16 hi = __float2bfloat16(w);
    __nv_bfloat16 lo = __float2bfloat16(w - __bfloat162float(hi));
    g_wbH[(kk * OO + o) * CC + c] = hi;
    g_wbL[(kk * OO + o) * CC + c] = lo;
}

// ============================================================
// Kernel 1b: pg_w (27,C,3,3) -> wpg2[kk][c][co32]
// ============================================================
__global__ void k_prep_wpg2(const float* __restrict__ pgw) {
    int i = blockIdx.x * 256 + threadIdx.x;
    if (i >= NKK * CC * 32) return;
    int co = i & 31;
    int c  = (i >> 5) & 63;
    int kk = i >> 11;
    g_wpg2[i] = (co < 27) ? pgw[co * QDIM + c * 9 + kk] : 0.f;
}

// ============================================================
// Kernel 2: offset/mask conv (R3 version, known-good)
// ============================================================
__global__ void __launch_bounds__(256) k_params(const float* __restrict__ pgb) {
    __shared__ float sp[64 * SPP];
    __shared__ float swp[64 * 32];
    int t = threadIdx.x;
    int blk = blockIdx.x;
    int wb = (blk & 1) * 64;
    int bh = blk >> 1;
    int b = bh >> 7, h = bh & 127;

    int og = t & 7;
    int pg = t >> 3;
    float a00, a01, a10, a11, a20, a21, a30, a31;
    {
        int c0 = og * 4;
        float b0 = (c0 + 0 < 27) ? __ldg(&pgb[c0 + 0]) : 0.f;
        float b1 = (c0 + 1 < 27) ? __ldg(&pgb[c0 + 1]) : 0.f;
        float b2 = (c0 + 2 < 27) ? __ldg(&pgb[c0 + 2]) : 0.f;
        float b3 = (c0 + 3 < 27) ? __ldg(&pgb[c0 + 3]) : 0.f;
        a00 = b0; a01 = b0; a10 = b1; a11 = b1;
        a20 = b2; a21 = b2; a30 = b3; a31 = b3;
    }
    const float* xb = &g_xT[(size_t)b * HH * WW * CC];

#pragma unroll 1
    for (int kk = 0; kk < NKK; kk++) {
        int dh = kk / 3 - 1, dw = kk % 3 - 1;
        int hh = h + dh;
        __syncthreads();
#pragma unroll
        for (int it = 0; it < 4; it++) {
            int idx = it * 256 + t;
            int pix = idx >> 4;
            int c4  = idx & 15;
            int gw = wb + pix + dw;
            float4 v = make_float4(0.f, 0.f, 0.f, 0.f);
            if (hh >= 0 && hh < HH && gw >= 0 && gw < WW)
                v = __ldg((const float4*)&xb[((size_t)hh * WW + gw) * CC + c4 * 4]);
            *(float4*)&sp[pix * SPP + c4 * 4] = v;
        }
#pragma unroll
        for (int it = 0; it < 2; it++) {
            int idx = it * 256 + t;
            ((float4*)swp)[idx] = __ldg(&((const float4*)g_wpg2)[kk * 512 + idx]);
        }
        __syncthreads();
#pragma unroll 8
        for (int ql = 0; ql < 64; ql++) {
            float4 wv = *(const float4*)&swp[ql * 32 + og * 4];
            float s0 = sp[(pg * 2 + 0) * SPP + ql];
            float s1 = sp[(pg * 2 + 1) * SPP + ql];
            a00 += wv.x * s0; a01 += wv.x * s1;
            a10 += wv.y * s0; a11 += wv.y * s1;
            a20 += wv.z * s0; a21 += wv.z * s1;
            a30 += wv.w * s0; a31 += wv.w * s1;
        }
    }
    int w0 = wb + pg * 2;
    int c0 = og * 4;
    float* p0 = &g_params[((size_t)bh * WW + w0) * 27];
    float* p1 = p0 + 27;
    if (c0 + 0 < 27) { p0[c0 + 0] = a00; p1[c0 + 0] = a01; }
    if (c0 + 1 < 27) { p0[c0 + 1] = a10; p1[c0 + 1] = a11; }
    if (c0 + 2 < 27) { p0[c0 + 2] = a20; p1[c0 + 2] = a21; }
    if (c0 + 3 < 27) { p0[c0 + 3] = a30; p1[c0 + 3] = a31; }
}

// ============================================================
// Kernel 3: fused bilinear gather + bf16-split mma.sync GEMM
// block = 64 px, 128 threads (4 warps). Warp w: px [w*16, w*16+16), all 64 o.
// K = 9 taps x 64 c. 3-pass split: AhBh + AhBl + AlBh.
// ============================================================
#define APITCH 72           // bf16 elems per row (144 B) -> LDSM conflict-free
#define A_BYTES (64 * APITCH * 2)    // 9216
#define DPITCH 68           // f32 pitch for epilogue staging (16B-aligned rows)
// smem blob offsets (bytes)
#define OFF_AH 0
#define OFF_AL (OFF_AH + A_BYTES)
#define OFF_BH (OFF_AL + A_BYTES)
#define OFF_BL (OFF_BH + A_BYTES)
#define OFF_PW (OFF_BL + A_BYTES)            // float[4][64]
#define OFF_PI (OFF_PW + 4 * 64 * 4)         // int[4][64]
#define SMEM_BYTES (OFF_PI + 4 * 64 * 4)     // 38912

__global__ void __launch_bounds__(128) k_main(const float* __restrict__ bias,
                                              float* __restrict__ out) {
    __shared__ __align__(16) unsigned char blob[SMEM_BYTES];
    u32 S = smem_u32(blob);
    float* pw = (float*)(blob + OFF_PW);
    int*   pi = (int*)(blob + OFF_PI);

    int t = threadIdx.x;
    int lane = t & 31;
    int warp = t >> 5;               // 0..3
    int blk = blockIdx.x;            // 1024
    int wb = (blk & 1) * 64;
    int bh = blk >> 1;
    int b = bh >> 7, h = bh & 127;

    const float* xb = &g_xT[(size_t)b * HH * WW * CC];

    float acc[8][4];                 // 8 n-tiles (o = j*8 + ...) x 4 f32
#pragma unroll
    for (int j = 0; j < 8; j++)
#pragma unroll
        for (int r = 0; r < 4; r++) acc[j][r] = 0.f;

    // ldmatrix lane addresses (constant per thread)
    u32 aAddrBase = S + OFF_AH + (u32)((warp * 16 + (lane & 15)) * (APITCH * 2))
                    + (u32)((lane >> 4) * 16);
    u32 bRowSel = (u32)(((lane & 7) + ((lane >> 4) & 1) * 8) * (APITCH * 2))
                  + (u32)(((lane >> 3) & 1) * 16);

#pragma unroll 1
    for (int kk = 0; kk < NKK; kk++) {
        __syncthreads();             // prev tap's MMA reads done
        // ---- phase A: sampling params (threads 0..63, one px each) ----
        if (t < 64) {
            int px = t;
            int w = wb + px;
            const float* pp = &g_params[((size_t)bh * WW + w) * 27];
            float dy = pp[2 * kk];
            float dx = pp[2 * kk + 1];
            float m  = pp[18 + kk];
            float mask = 1.f / (1.f + expf(-m));
            float ys = (float)(h - 1 + kk / 3) + dy;
            float xs = (float)(w - 1 + kk % 3) + dx;
            float y0f = floorf(ys), x0f = floorf(xs);
            float ly = ys - y0f, lx = xs - x0f;
            int y0 = (int)y0f, x0 = (int)x0f;
            float vy0 = (y0 >= 0 && y0 < HH) ? 1.f : 0.f;
            float vy1 = (y0 + 1 >= 0 && y0 + 1 < HH) ? 1.f : 0.f;
            float vx0 = (x0 >= 0 && x0 < WW) ? 1.f : 0.f;
            float vx1 = (x0 + 1 >= 0 && x0 + 1 < WW) ? 1.f : 0.f;
            pw[0 * 64 + px] = (1.f - ly) * (1.f - lx) * mask * vy0 * vx0;
            pw[1 * 64 + px] = (1.f - ly) * lx         * mask * vy0 * vx1;
            pw[2 * 64 + px] = ly * (1.f - lx)         * mask * vy1 * vx0;
            pw[3 * 64 + px] = ly * lx                 * mask * vy1 * vx1;
            pi[0 * 64 + px] = min(max(y0, 0), HH - 1) * WW;
            pi[1 * 64 + px] = min(max(y0 + 1, 0), HH - 1) * WW;
            pi[2 * 64 + px] = min(max(x0, 0), WW - 1);
            pi[3 * 64 + px] = min(max(x0 + 1, 0), WW - 1);
        }
        // ---- stage B hi/lo: 64 o x 64 c -> pitch 72 ----
        {
            const uint4* gh = (const uint4*)&g_wbH[(size_t)kk * OO * CC];
            const uint4* gl = (const uint4*)&g_wbL[(size_t)kk * OO * CC];
#pragma unroll
            for (int it = 0; it < 4; it++) {
                int idx = it * 128 + t;          // 512 uint4 per buffer
                int row = idx >> 3;              // o
                int col = idx & 7;               // 16B unit
                uint4 vh = __ldg(&gh[idx]);
                uint4 vl = __ldg(&gl[idx]);
                *(uint4*)(blob + OFF_BH + row * (APITCH * 2) + col * 16) = vh;
                *(uint4*)(blob + OFF_BL + row * (APITCH * 2) + col * 16) = vl;
            }
        }
        __syncthreads();             // pw/pi + B visible

        // ---- gather: 64 px x 16 c4, bf16 split into A hi/lo ----
#pragma unroll
        for (int it = 0; it < 8; it++) {
            int idx = it * 128 + t;
            int c4 = idx & 15;
            int px = idx >> 4;
            float w00 = pw[0 * 64 + px];
            float w01 = pw[1 * 64 + px];
            float w10 = pw[2 * 64 + px];
            float w11 = pw[3 * 64 + px];
            int r0  = pi[0 * 64 + px];
            int r1  = pi[1 * 64 + px];
            int x0c = pi[2 * 64 + px];
            int x1c = pi[3 * 64 + px];
            float4 g00 = __ldg((const float4*)&xb[(size_t)(r0 + x0c) * CC + c4 * 4]);
            float4 g01 = __ldg((const float4*)&xb[(size_t)(r0 + x1c) * CC + c4 * 4]);
            float4 g10 = __ldg((const float4*)&xb[(size_t)(r1 + x0c) * CC + c4 * 4]);
            float4 g11 = __ldg((const float4*)&xb[(size_t)(r1 + x1c) * CC + c4 * 4]);
            float v0 = w00 * g00.x + w01 * g01.x + w10 * g10.x + w11 * g11.x;
            float v1 = w00 * g00.y + w01 * g01.y + w10 * g10.y + w11 * g11.y;
            float v2 = w00 * g00.z + w01 * g01.z + w10 * g10.z + w11 * g11.z;
            float v3 = w00 * g00.w + w01 * g01.w + w10 * g10.w + w11 * g11.w;
            __nv_bfloat162 h01 = __floats2bfloat162_rn(v0, v1);
            __nv_bfloat162 h23 = __floats2bfloat162_rn(v2, v3);
            float l0 = v0 - __bfloat162float(h01.x);
            float l1 = v1 - __bfloat162float(h01.y);
            float l2 = v2 - __bfloat162float(h23.x);
            float l3 = v3 - __bfloat162float(h23.y);
            __nv_bfloat162 L01 = __floats2bfloat162_rn(l0, l1);
            __nv_bfloat162 L23 = __floats2bfloat162_rn(l2, l3);
            uint2 uh = make_uint2(*(u32*)&h01, *(u32*)&h23);
            uint2 ul = make_uint2(*(u32*)&L01, *(u32*)&L23);
            int off = px * (APITCH * 2) + c4 * 8;
            *(uint2*)(blob + OFF_AH + off) = uh;
            *(uint2*)(blob + OFF_AL + off) = ul;
        }
        __syncthreads();

        // ---- MMA: 4 k-steps x 4 n-pairs x 3 split passes ----
#pragma unroll
        for (int ks = 0; ks < 4; ks++) {
            u32 aa = aAddrBase + ks * 32;
            u32 ah0, ah1, ah2, ah3, al0, al1, al2, al3;
            LDSM4(ah0, ah1, ah2, ah3, aa);
            LDSM4(al0, al1, al2, al3, aa + A_BYTES);
#pragma unroll
            for (int np = 0; np < 4; np++) {
                u32 ba = S + OFF_BH + (u32)(np * 16 * (APITCH * 2)) + bRowSel + ks * 32;
                u32 bh0, bh1, bh2, bh3, bl0, bl1, bl2, bl3;
                LDSM4(bh0, bh1, bh2, bh3, ba);
                LDSM4(bl0, bl1, bl2, bl3, ba + A_BYTES);
                mma16816(acc[np * 2 + 0], ah0, ah1, ah2, ah3, bh0, bh1);
                mma16816(acc[np * 2 + 1], ah0, ah1, ah2, ah3, bh2, bh3);
                mma16816(acc[np * 2 + 0], ah0, ah1, ah2, ah3, bl0, bl1);
                mma16816(acc[np * 2 + 1], ah0, ah1, ah2, ah3, bl2, bl3);
                mma16816(acc[np * 2 + 0], al0, al1, al2, al3, bh0, bh1);
                mma16816(acc[np * 2 + 1], al0, al1, al2, al3, bh2, bh3);
            }
        }
    }

    // ---- epilogue: stage D in smem [o][px] (pitch 68), coalesced write ----
    __syncthreads();
    float* sD = (float*)blob;        // [64 o][DPITCH px]  (17.4 KB)
    {
        int px0 = warp * 16 + (lane >> 2);
#pragma unroll
        for (int j = 0; j < 8; j++) {
            int o = j * 8 + 2 * (lane & 3);
            sD[o * DPITCH + px0]           = acc[j][0];
            sD[(o + 1) * DPITCH + px0]     = acc[j][1];
            sD[o * DPITCH + px0 + 8]       = acc[j][2];
            sD[(o + 1) * DPITCH + px0 + 8] = acc[j][3];
        }
    }
    __syncthreads();
    {
        int o = t >> 1;
        int half = t & 1;
        float bv = __ldg(&bias[o]);
        size_t base = ((size_t)(b * OO + o) * HH + h) * WW + wb + half * 32;
        const float* src = &sD[o * DPITCH + half * 32];
#pragma unroll
        for (int i = 0; i < 8; i++) {
            float4 v = *(const float4*)&src[i * 4];
            v.x += bv; v.y += bv; v.z += bv; v.w += bv;
            *(float4*)&out[base + i * 4] = v;
        }
    }
}

// ============================================================
extern "C" void kernel_launch(void* const* d_in, const int* in_sizes, int n_in,
                              void* d_out, int out_size) {
    const float* x      = (const float*)d_in[0];
    const float* weight = (const float*)d_in[1];
    const float* bias   = (const float*)d_in[2];
    const float* pg_w   = (const float*)d_in[3];
    const float* pg_b   = (const float*)d_in[4];
    float* out = (float*)d_out;

    k_transpose_x<<<BB * HH, 256>>>(x);
    k_prep_wb<<<(NKK * OO * CC + 255) / 256, 256>>>(weight);
    k_prep_wpg2<<<(NKK * CC * 32 + 255) / 256, 256>>>(pg_w);
    k_params<<<BB * HH * 2, 256>>>(pg_b);
    k_main<<<BB * HH * 2, 128>>>(bias, out);
}

// round 8
// speedup vs baseline: 3.4266x; 1.4813x over previous
#include <cuda_runtime.h>
#include <cuda_bf16.h>
#include <math.h>

#define BB 4
#define CC 64
#define HH 128
#define WW 128
#define OO 64
#define NKK 9
#define QDIM 576
#define NPIX (BB*HH*WW)     // 65536

typedef unsigned int u32;

// ---- device scratch ----
__device__ float g_xT[BB*HH*WW*CC];             // NHWC x
__device__ float g_params[27*NPIX];             // planar [co][pix]
__device__ __nv_bfloat16 g_wbH[NKK*OO*CC];      // main weights bf16 hi, [kk][o][c]
__device__ __nv_bfloat16 g_wbL[NKK*OO*CC];      // main weights bf16 lo
__device__ __nv_bfloat16 g_wpgH[NKK*32*CC];     // pg weights bf16 hi, [kk][co32][c]
__device__ __nv_bfloat16 g_wpgL[NKK*32*CC];     // pg weights bf16 lo

__device__ __forceinline__ u32 smem_u32(const void* p) {
    u32 a;
    asm("{ .reg .u64 t; cvta.to.shared.u64 t, %1; cvt.u32.u64 %0, t; }" : "=r"(a) : "l"(p));
    return a;
}

#define LDSM4(r0, r1, r2, r3, addr) \
    asm volatile("ldmatrix.sync.aligned.m8n8.x4.shared.b16 {%0,%1,%2,%3},[%4];" \
        : "=r"(r0), "=r"(r1), "=r"(r2), "=r"(r3) : "r"(addr))

__device__ __forceinline__ void mma16816(float* d, u32 a0, u32 a1, u32 a2, u32 a3,
                                         u32 b0, u32 b1) {
    asm volatile(
        "mma.sync.aligned.m16n8k16.row.col.f32.bf16.bf16.f32 "
        "{%0,%1,%2,%3},{%4,%5,%6,%7},{%8,%9},{%0,%1,%2,%3};"
        : "+f"(d[0]), "+f"(d[1]), "+f"(d[2]), "+f"(d[3])
        : "r"(a0), "r"(a1), "r"(a2), "r"(a3), "r"(b0), "r"(b1));
}

// ============================================================
// Kernel 0: x NCHW -> NHWC
// ============================================================
__global__ void k_transpose_x(const float* __restrict__ x) {
    __shared__ float tile[64][129];
    int bh = blockIdx.x;
    int b = bh >> 7, h = bh & 127;
    int t = threadIdx.x;
    for (int i = t; i < 64 * 128; i += 256) {
        int c = i >> 7, w = i & 127;
        tile[c][w] = x[((size_t)(b * CC + c) * HH + h) * WW + w];
    }
    __syncthreads();
    for (int i = t; i < 64 * 128; i += 256) {
        int w = i >> 6, c = i & 63;
        g_xT[((size_t)bh * WW + w) * CC + c] = tile[c][w];
    }
}

// ============================================================
// Kernel 1: weight (O,C,3,3) -> bf16 hi/lo [kk][o][c]
// ============================================================
__global__ void k_prep_wb(const float* __restrict__ wgt) {
    int i = blockIdx.x * 256 + threadIdx.x;
    if (i >= NKK * OO * CC) return;
    int kk = i % 9;
    int c  = (i / 9) & 63;
    int o  = i / (9 * 64);
    float w = wgt[i];
    __nv_bfloat16 hi = __float2bfloat16(w);
    __nv_bfloat16 lo = __float2bfloat16(w - __bfloat162float(hi));
    g_wbH[(kk * OO + o) * CC + c] = hi;
    g_wbL[(kk * OO + o) * CC + c] = lo;
}

// ============================================================
// Kernel 1b: pg_w (27,C,3,3) -> bf16 hi/lo [kk][co32][c]
// ============================================================
__global__ void k_prep_wpg(const float* __restrict__ pgw) {
    int i = blockIdx.x * 256 + threadIdx.x;     // 9*32*64
    if (i >= NKK * 32 * CC) return;
    int c  = i & 63;
    int co = (i >> 6) & 31;
    int kk = i >> 11;
    float w = (co < 27) ? pgw[co * QDIM + c * 9 + kk] : 0.f;
    __nv_bfloat16 hi = __float2bfloat16(w);
    __nv_bfloat16 lo = __float2bfloat16(w - __bfloat162float(hi));
    g_wpgH[i] = hi;
    g_wpgL[i] = lo;
}

// ============================================================
// shared constants for MMA kernels
// ============================================================
#define APITCH 72                    // bf16/row (144 B)
#define A_BYTES (64 * APITCH * 2)    // 9216
#define DPITCH 68

// ============================================================
// Kernel 2: offset/mask conv via bf16-split mma.sync
// block = 64 px, 128 threads (4 warps). Warp w: px [16w,16w+16), co 0..31.
// ============================================================
#define P_OFF_AH 0
#define P_OFF_AL (P_OFF_AH + A_BYTES)
#define P_OFF_BH (P_OFF_AL + A_BYTES)                 // 32 x 144B = 4608
#define P_OFF_BL (P_OFF_BH + 32 * APITCH * 2)
#define P_SMEM   (P_OFF_BL + 32 * APITCH * 2)         // 27648

__global__ void __launch_bounds__(128) k_params(const float* __restrict__ pgb) {
    __shared__ __align__(16) unsigned char blob[P_SMEM];
    u32 S = smem_u32(blob);
    int t = threadIdx.x;
    int lane = t & 31;
    int warp = t >> 5;
    int blk = blockIdx.x;            // 1024
    int wb = (blk & 1) * 64;
    int bh = blk >> 1;
    int b = bh >> 7, h = bh & 127;

    const float* xb = &g_xT[(size_t)b * HH * WW * CC];

    float acc[4][4];
#pragma unroll
    for (int j = 0; j < 4; j++)
#pragma unroll
        for (int r = 0; r < 4; r++) acc[j][r] = 0.f;

    u32 aAddrBase = S + P_OFF_AH + (u32)((warp * 16 + (lane & 15)) * (APITCH * 2))
                    + (u32)((lane >> 4) * 16);
    u32 bRowSel = (u32)(((lane & 7) + ((lane >> 4) & 1) * 8) * (APITCH * 2))
                  + (u32)(((lane >> 3) & 1) * 16);

#pragma unroll 1
    for (int kk = 0; kk < NKK; kk++) {
        int dh = kk / 3 - 1, dw = kk % 3 - 1;
        int hh = h + dh;
        __syncthreads();             // prev MMA reads done
        // ---- stage A: shifted patch 64 px x 64 c, bf16 hi/lo ----
#pragma unroll
        for (int it = 0; it < 8; it++) {
            int idx = it * 128 + t;
            int c4 = idx & 15;
            int px = idx >> 4;
            int gw = wb + px + dw;
            float4 g = make_float4(0.f, 0.f, 0.f, 0.f);
            if (hh >= 0 && hh < HH && gw >= 0 && gw < WW)
                g = __ldg((const float4*)&xb[((size_t)hh * WW + gw) * CC + c4 * 4]);
            __nv_bfloat162 h01 = __floats2bfloat162_rn(g.x, g.y);
            __nv_bfloat162 h23 = __floats2bfloat162_rn(g.z, g.w);
            float l0 = g.x - __bfloat162float(h01.x);
            float l1 = g.y - __bfloat162float(h01.y);
            float l2 = g.z - __bfloat162float(h23.x);
            float l3 = g.w - __bfloat162float(h23.y);
            __nv_bfloat162 L01 = __floats2bfloat162_rn(l0, l1);
            __nv_bfloat162 L23 = __floats2bfloat162_rn(l2, l3);
            uint2 uh = make_uint2(*(u32*)&h01, *(u32*)&h23);
            uint2 ul = make_uint2(*(u32*)&L01, *(u32*)&L23);
            int off = px * (APITCH * 2) + c4 * 8;
            *(uint2*)(blob + P_OFF_AH + off) = uh;
            *(uint2*)(blob + P_OFF_AL + off) = ul;
        }
        // ---- stage B: 32 co x 64 c (256 uint4 per buffer) ----
        {
            const uint4* gh = (const uint4*)&g_wpgH[(size_t)kk * 32 * CC];
            const uint4* gl = (const uint4*)&g_wpgL[(size_t)kk * 32 * CC];
#pragma unroll
            for (int it = 0; it < 2; it++) {
                int idx = it * 128 + t;
                int row = idx >> 3;
                int col = idx & 7;
                uint4 vh = __ldg(&gh[idx]);
                uint4 vl = __ldg(&gl[idx]);
                *(uint4*)(blob + P_OFF_BH + row * (APITCH * 2) + col * 16) = vh;
                *(uint4*)(blob + P_OFF_BL + row * (APITCH * 2) + col * 16) = vl;
            }
        }
        __syncthreads();
        // ---- MMA: 4 ksteps x 2 n-pairs x 3 passes ----
#pragma unroll
        for (int ks = 0; ks < 4; ks++) {
            u32 aa = aAddrBase + ks * 32;
            u32 ah0, ah1, ah2, ah3, al0, al1, al2, al3;
            LDSM4(ah0, ah1, ah2, ah3, aa);
            LDSM4(al0, al1, al2, al3, aa + A_BYTES);
#pragma unroll
            for (int np = 0; np < 2; np++) {
                u32 ba = S + P_OFF_BH + (u32)(np * 16 * (APITCH * 2)) + bRowSel + ks * 32;
                u32 bh0, bh1, bh2, bh3, bl0, bl1, bl2, bl3;
                LDSM4(bh0, bh1, bh2, bh3, ba);
                LDSM4(bl0, bl1, bl2, bl3, ba + 32 * APITCH * 2 /* -> BL */);
                mma16816(acc[np * 2 + 0], ah0, ah1, ah2, ah3, bh0, bh1);
                mma16816(acc[np * 2 + 1], ah0, ah1, ah2, ah3, bh2, bh3);
                mma16816(acc[np * 2 + 0], ah0, ah1, ah2, ah3, bl0, bl1);
                mma16816(acc[np * 2 + 1], ah0, ah1, ah2, ah3, bl2, bl3);
                mma16816(acc[np * 2 + 0], al0, al1, al2, al3, bh0, bh1);
                mma16816(acc[np * 2 + 1], al0, al1, al2, al3, bh2, bh3);
            }
        }
    }

    // ---- epilogue: stage sD[32co][68px], planar coalesced write ----
    __syncthreads();
    float* sD = (float*)blob;
    {
        int px0 = warp * 16 + (lane >> 2);
#pragma unroll
        for (int j = 0; j < 4; j++) {
            int co = j * 8 + 2 * (lane & 3);
            sD[co * DPITCH + px0]           = acc[j][0];
            sD[(co + 1) * DPITCH + px0]     = acc[j][1];
            sD[co * DPITCH + px0 + 8]       = acc[j][2];
            sD[(co + 1) * DPITCH + px0 + 8] = acc[j][3];
        }
    }
    __syncthreads();
#pragma unroll
    for (int i = 0; i < 14; i++) {
        int idx = i * 128 + t;               // 27*64 = 1728
        if (idx < 1728) {
            int co = idx >> 6;
            int px = idx & 63;
            g_params[(size_t)co * NPIX + (size_t)bh * WW + wb + px] =
                sD[co * DPITCH + px] + __ldg(&pgb[co]);
        }
    }
}

// ============================================================
// Kernel 3: fused bilinear gather + bf16-split mma.sync GEMM (R7, planar params)
// ============================================================
#define OFF_AH 0
#define OFF_AL (OFF_AH + A_BYTES)
#define OFF_BH (OFF_AL + A_BYTES)
#define OFF_BL (OFF_BH + A_BYTES)
#define OFF_PW (OFF_BL + A_BYTES)            // float[4][64]
#define OFF_PI (OFF_PW + 4 * 64 * 4)         // int[4][64]
#define SMEM_BYTES (OFF_PI + 4 * 64 * 4)     // 38912

__global__ void __launch_bounds__(128) k_main(const float* __restrict__ bias,
                                              float* __restrict__ out) {
    __shared__ __align__(16) unsigned char blob[SMEM_BYTES];
    u32 S = smem_u32(blob);
    float* pw = (float*)(blob + OFF_PW);
    int*   pi = (int*)(blob + OFF_PI);

    int t = threadIdx.x;
    int lane = t & 31;
    int warp = t >> 5;
    int blk = blockIdx.x;
    int wb = (blk & 1) * 64;
    int bh = blk >> 1;
    int b = bh >> 7, h = bh & 127;

    const float* xb = &g_xT[(size_t)b * HH * WW * CC];

    float acc[8][4];
#pragma unroll
    for (int j = 0; j < 8; j++)
#pragma unroll
        for (int r = 0; r < 4; r++) acc[j][r] = 0.f;

    u32 aAddrBase = S + OFF_AH + (u32)((warp * 16 + (lane & 15)) * (APITCH * 2))
                    + (u32)((lane >> 4) * 16);
    u32 bRowSel = (u32)(((lane & 7) + ((lane >> 4) & 1) * 8) * (APITCH * 2))
                  + (u32)(((lane >> 3) & 1) * 16);

#pragma unroll 1
    for (int kk = 0; kk < NKK; kk++) {
        __syncthreads();
        // ---- phase A: sampling params (threads 0..63) ----
        if (t < 64) {
            int px = t;
            int w = wb + px;
            size_t pixi = (size_t)bh * WW + w;
            float dy = __ldg(&g_params[(size_t)(2 * kk) * NPIX + pixi]);
            float dx = __ldg(&g_params[(size_t)(2 * kk + 1) * NPIX + pixi]);
            float m  = __ldg(&g_params[(size_t)(18 + kk) * NPIX + pixi]);
            float mask = 1.f / (1.f + expf(-m));
            float ys = (float)(h - 1 + kk / 3) + dy;
            float xs = (float)(w - 1 + kk % 3) + dx;
            float y0f = floorf(ys), x0f = floorf(xs);
            float ly = ys - y0f, lx = xs - x0f;
            int y0 = (int)y0f, x0 = (int)x0f;
            float vy0 = (y0 >= 0 && y0 < HH) ? 1.f : 0.f;
            float vy1 = (y0 + 1 >= 0 && y0 + 1 < HH) ? 1.f : 0.f;
            float vx0 = (x0 >= 0 && x0 < WW) ? 1.f : 0.f;
            float vx1 = (x0 + 1 >= 0 && x0 + 1 < WW) ? 1.f : 0.f;
            pw[0 * 64 + px] = (1.f - ly) * (1.f - lx) * mask * vy0 * vx0;
            pw[1 * 64 + px] = (1.f - ly) * lx         * mask * vy0 * vx1;
            pw[2 * 64 + px] = ly * (1.f - lx)         * mask * vy1 * vx0;
            pw[3 * 64 + px] = ly * lx                 * mask * vy1 * vx1;
            pi[0 * 64 + px] = min(max(y0, 0), HH - 1) * WW;
            pi[1 * 64 + px] = min(max(y0 + 1, 0), HH - 1) * WW;
            pi[2 * 64 + px] = min(max(x0, 0), WW - 1);
            pi[3 * 64 + px] = min(max(x0 + 1, 0), WW - 1);
        }
        // ---- stage B hi/lo ----
        {
            const uint4* gh = (const uint4*)&g_wbH[(size_t)kk * OO * CC];
            const uint4* gl = (const uint4*)&g_wbL[(size_t)kk * OO * CC];
#pragma unroll
            for (int it = 0; it < 4; it++) {
                int idx = it * 128 + t;
                int row = idx >> 3;
                int col = idx & 7;
                uint4 vh = __ldg(&gh[idx]);
                uint4 vl = __ldg(&gl[idx]);
                *(uint4*)(blob + OFF_BH + row * (APITCH * 2) + col * 16) = vh;
                *(uint4*)(blob + OFF_BL + row * (APITCH * 2) + col * 16) = vl;
            }
        }
        __syncthreads();

        // ---- gather: 64 px x 16 c4 ----
#pragma unroll
        for (int it = 0; it < 8; it++) {
            int idx = it * 128 + t;
            int c4 = idx & 15;
            int px = idx >> 4;
            float w00 = pw[0 * 64 + px];
            float w01 = pw[1 * 64 + px];
            float w10 = pw[2 * 64 + px];
            float w11 = pw[3 * 64 + px];
            int r0  = pi[0 * 64 + px];
            int r1  = pi[1 * 64 + px];
            int x0c = pi[2 * 64 + px];
            int x1c = pi[3 * 64 + px];
            float4 g00 = __ldg((const float4*)&xb[(size_t)(r0 + x0c) * CC + c4 * 4]);
            float4 g01 = __ldg((const float4*)&xb[(size_t)(r0 + x1c) * CC + c4 * 4]);
            float4 g10 = __ldg((const float4*)&xb[(size_t)(r1 + x0c) * CC + c4 * 4]);
            float4 g11 = __ldg((const float4*)&xb[(size_t)(r1 + x1c) * CC + c4 * 4]);
            float v0 = w00 * g00.x + w01 * g01.x + w10 * g10.x + w11 * g11.x;
            float v1 = w00 * g00.y + w01 * g01.y + w10 * g10.y + w11 * g11.y;
            float v2 = w00 * g00.z + w01 * g01.z + w10 * g10.z + w11 * g11.z;
            float v3 = w00 * g00.w + w01 * g01.w + w10 * g10.w + w11 * g11.w;
            __nv_bfloat162 h01 = __floats2bfloat162_rn(v0, v1);
            __nv_bfloat162 h23 = __floats2bfloat162_rn(v2, v3);
            float l0 = v0 - __bfloat162float(h01.x);
            float l1 = v1 - __bfloat162float(h01.y);
            float l2 = v2 - __bfloat162float(h23.x);
            float l3 = v3 - __bfloat162float(h23.y);
            __nv_bfloat162 L01 = __floats2bfloat162_rn(l0, l1);
            __nv_bfloat162 L23 = __floats2bfloat162_rn(l2, l3);
            uint2 uh = make_uint2(*(u32*)&h01, *(u32*)&h23);
            uint2 ul = make_uint2(*(u32*)&L01, *(u32*)&L23);
            int off = px * (APITCH * 2) + c4 * 8;
            *(uint2*)(blob + OFF_AH + off) = uh;
            *(uint2*)(blob + OFF_AL + off) = ul;
        }
        __syncthreads();

        // ---- MMA ----
#pragma unroll
        for (int ks = 0; ks < 4; ks++) {
            u32 aa = aAddrBase + ks * 32;
            u32 ah0, ah1, ah2, ah3, al0, al1, al2, al3;
            LDSM4(ah0, ah1, ah2, ah3, aa);
            LDSM4(al0, al1, al2, al3, aa + A_BYTES);
#pragma unroll
            for (int np = 0; np < 4; np++) {
                u32 ba = S + OFF_BH + (u32)(np * 16 * (APITCH * 2)) + bRowSel + ks * 32;
                u32 bh0, bh1, bh2, bh3, bl0, bl1, bl2, bl3;
                LDSM4(bh0, bh1, bh2, bh3, ba);
                LDSM4(bl0, bl1, bl2, bl3, ba + A_BYTES);
                mma16816(acc[np * 2 + 0], ah0, ah1, ah2, ah3, bh0, bh1);
                mma16816(acc[np * 2 + 1], ah0, ah1, ah2, ah3, bh2, bh3);
                mma16816(acc[np * 2 + 0], ah0, ah1, ah2, ah3, bl0, bl1);
                mma16816(acc[np * 2 + 1], ah0, ah1, ah2, ah3, bl2, bl3);
                mma16816(acc[np * 2 + 0], al0, al1, al2, al3, bh0, bh1);
                mma16816(acc[np * 2 + 1], al0, al1, al2, al3, bh2, bh3);
            }
        }
    }

    // ---- epilogue ----
    __syncthreads();
    float* sD = (float*)blob;
    {
        int px0 = warp * 16 + (lane >> 2);
#pragma unroll
        for (int j = 0; j < 8; j++) {
            int o = j * 8 + 2 * (lane & 3);
            sD[o * DPITCH + px0]           = acc[j][0];
            sD[(o + 1) * DPITCH + px0]     = acc[j][1];
            sD[o * DPITCH + px0 + 8]       = acc[j][2];
            sD[(o + 1) * DPITCH + px0 + 8] = acc[j][3];
        }
    }
    __syncthreads();
    {
        int o = t >> 1;
        int half = t & 1;
        float bv = __ldg(&bias[o]);
        size_t base = ((size_t)(b * OO + o) * HH + h) * WW + wb + half * 32;
        const float* src = &sD[o * DPITCH + half * 32];
#pragma unroll
        for (int i = 0; i < 8; i++) {
            float4 v = *(const float4*)&src[i * 4];
            v.x += bv; v.y += bv; v.z += bv; v.w += bv;
            *(float4*)&out[base + i * 4] = v;
        }
    }
}

// ============================================================
extern "C" void kernel_launch(void* const* d_in, const int* in_sizes, int n_in,
                              void* d_out, int out_size) {
    const float* x      = (const float*)d_in[0];
    const float* weight = (const float*)d_in[1];
    const float* bias   = (const float*)d_in[2];
    const float* pg_w   = (const float*)d_in[3];
    const float* pg_b   = (const float*)d_in[4];
    float* out = (float*)d_out;

    k_transpose_x<<<BB * HH, 256>>>(x);
    k_prep_wb<<<(NKK * OO * CC + 255) / 256, 256>>>(weight);
    k_prep_wpg<<<(NKK * 32 * CC + 255) / 256, 256>>>(pg_w);
    k_params<<<BB * HH * 2, 128>>>(pg_b);
    k_main<<<BB * HH * 2, 128>>>(bias, out);
}